// round 3
// baseline (speedup 1.0000x reference)
#include <cuda_runtime.h>
#include <cuda_bf16.h>
#include <math.h>

// ---------------- problem constants ----------------
#define NQ   32768
#define NE   262144
#define S    32768

// ---------------- scratch (device globals; 16B aligned for float4 access) ----------------
__device__ __align__(16) float g_Wc[192 * 384];          // proj_w @ msg0_w_top
__device__ __align__(16) float g_bc[384];                // proj_b @ msg0_w_top + msg0_b
__device__ __align__(16) float g_QE[NQ * 192];           // sincos embed
__device__ __align__(16) float g_A1[S * 384];            // x @ Wc + bc
__device__ __align__(16) float g_A2[NQ * 384];           // QE @ msg0_w_bot
__device__ __align__(16) float g_H0[(size_t)NE * 384];   // gelu(A1[g]+A2[q]); later reused for H2
__device__ __align__(16) float g_H1[(size_t)NE * 384];   // gelu(H0 @ msg1 + b1)
__device__ __align__(16) float g_M [NQ * 192];           // segment mean
__device__ __align__(16) float g_T [NQ * 192];           // gelu(M @ pred0 + b)
__device__ int   g_start[NQ + 1];                        // segment offsets (qidx sorted)

__device__ __forceinline__ float gelu_f(float x) {
    return 0.5f * x * (1.0f + erff(x * 0.70710678118654752f));
}

// ---------------- weight folding: Wc = proj_w @ msg0_w[0:192,:] ----------------
__global__ void fold_w_kernel(const float* __restrict__ proj_w,
                              const float* __restrict__ msg0_w) {
    int idx = blockIdx.x * blockDim.x + threadIdx.x;
    if (idx >= 192 * 384) return;
    int i = idx / 384, n = idx % 384;
    float s = 0.f;
    #pragma unroll 4
    for (int j = 0; j < 192; j++)
        s += proj_w[i * 192 + j] * msg0_w[j * 384 + n];
    g_Wc[idx] = s;
}

__global__ void fold_b_kernel(const float* __restrict__ proj_b,
                              const float* __restrict__ msg0_w,
                              const float* __restrict__ msg0_b) {
    int n = blockIdx.x * blockDim.x + threadIdx.x;
    if (n >= 384) return;
    float s = msg0_b[n];
    #pragma unroll 4
    for (int j = 0; j < 192; j++)
        s += proj_b[j] * msg0_w[j * 384 + n];
    g_bc[n] = s;
}

// ---------------- sincos positional embedding ----------------
__global__ void qe_kernel(const float* __restrict__ query_pos) {
    int idx = blockIdx.x * blockDim.x + threadIdx.x;
    if (idx >= NQ * 192) return;
    int q = idx / 192, c = idx % 192;
    int d = c / 64, j = c % 64;
    int i = (j < 32) ? j : j - 32;
    float coord = query_pos[q * 3 + d];
    float expo  = (2.0f * (float)i) / 64.0f;
    float omega = powf(10000.0f, -expo);
    float a = coord * omega;
    g_QE[idx] = (j < 32) ? sinf(a) : cosf(a);
}

// ---------------- generic fp32 SGEMM: C[M,N] = op(A[M,K] @ B[K,N] + bias) ----------------
// 128x128 tile, BK=8, 8x8 per thread, 256 threads. M must be a multiple of 128.
// Requires: K % 8 == 0, N % 4 == 0, A rows 16B-aligned (K % 4 == 0), B rows 16B-aligned.
template <bool GELU>
__global__ __launch_bounds__(256)
void sgemm_kernel(const float* __restrict__ A, const float* __restrict__ B,
                  const float* __restrict__ bias, float* __restrict__ C,
                  int M, int N, int K) {
    const int BM = 128, BN = 128, BK = 8, TM = 8, TN = 8;
    __shared__ float As[BK][BM];
    __shared__ float Bs[BK][BN];

    int tid = threadIdx.x;
    int bm = blockIdx.y * BM;
    int bn = blockIdx.x * BN;
    int tr = tid / 16;            // 0..15
    int tc = tid % 16;            // 0..15

    float acc[TM][TN];
    #pragma unroll
    for (int i = 0; i < TM; i++)
        #pragma unroll
        for (int j = 0; j < TN; j++) acc[i][j] = 0.f;

    int aRow = tid >> 1;          // 0..127
    int aCol = (tid & 1) * 4;     // 0 or 4
    int bRow = tid >> 5;          // 0..7
    int bCol = (tid & 31) * 4;    // 0..124

    const float* Abase = A + (size_t)bm * K;

    for (int kt = 0; kt < K; kt += BK) {
        float4 av = *(const float4*)(Abase + (size_t)aRow * K + kt + aCol);
        As[aCol + 0][aRow] = av.x;
        As[aCol + 1][aRow] = av.y;
        As[aCol + 2][aRow] = av.z;
        As[aCol + 3][aRow] = av.w;

        float4 bv = make_float4(0.f, 0.f, 0.f, 0.f);
        int gcol = bn + bCol;
        if (gcol < N)  // N % 4 == 0 so full float4 is in-bounds
            bv = *(const float4*)(B + (size_t)(kt + bRow) * N + gcol);
        *(float4*)&Bs[bRow][bCol] = bv;

        __syncthreads();

        #pragma unroll
        for (int k = 0; k < BK; k++) {
            float rm[TM], rn[TN];
            #pragma unroll
            for (int i = 0; i < TM; i++) rm[i] = As[k][tr * TM + i];
            #pragma unroll
            for (int j = 0; j < TN; j++) rn[j] = Bs[k][tc * TN + j];
            #pragma unroll
            for (int i = 0; i < TM; i++)
                #pragma unroll
                for (int j = 0; j < TN; j++)
                    acc[i][j] = fmaf(rm[i], rn[j], acc[i][j]);
        }
        __syncthreads();
    }

    #pragma unroll
    for (int i = 0; i < TM; i++) {
        int row = bm + tr * TM + i;
        #pragma unroll
        for (int j = 0; j < TN; j++) {
            int col = bn + tc * TN + j;
            if (col < N) {
                float v = acc[i][j];
                if (bias) v += bias[col];
                if (GELU) v = gelu_f(v);
                C[(size_t)row * N + col] = v;
            }
        }
    }
}

// ---------------- edge layer 0: H0[e] = gelu(A1[g[e]] + A2[q[e]]) ----------------
// edges are int32 pairs (q, g). One warp handles 96 channels x ... layout:
// simple elementwise over NE*384 with per-element edge fetch via __ldg (L1/L2 cached).
__global__ void edge0_kernel(const int* __restrict__ edges) {
    long long idx = (long long)blockIdx.x * blockDim.x + threadIdx.x;
    if (idx >= (long long)NE * 384) return;
    int e = (int)(idx / 384);
    int c = (int)(idx % 384);
    int q = __ldg(&edges[2 * e]);
    int g = __ldg(&edges[2 * e + 1]);
    float v = g_A1[(size_t)g * 384 + c] + g_A2[(size_t)q * 384 + c];
    g_H0[idx] = gelu_f(v);
}

// ---------------- segment offsets (qidx is sorted ascending) ----------------
__global__ void segstart_kernel(const int* __restrict__ edges) {
    int q = blockIdx.x * blockDim.x + threadIdx.x;
    if (q > NQ) return;
    if (q == NQ) { g_start[NQ] = NE; return; }
    int lo = 0, hi = NE;
    while (lo < hi) {
        int mid = (lo + hi) >> 1;
        int v = edges[2 * mid];
        if (v < q) lo = mid + 1; else hi = mid;
    }
    g_start[q] = lo;
}

// ---------------- segment mean over H2 (stored in g_H0) ----------------
__global__ void segmean_kernel(const float* __restrict__ H2) {
    int q = blockIdx.x;
    int c = threadIdx.x;   // 0..191
    int s = g_start[q], e = g_start[q + 1];
    float sum = 0.f;
    for (int i = s; i < e; i++)
        sum += H2[(size_t)i * 192 + c];
    float cnt = (float)(e - s);
    g_M[q * 192 + c] = sum / fmaxf(cnt, 1.0f);
}

// ---------------- final tiny projection: out = T @ pred1_w + pred1_b ----------------
__global__ void outk_kernel(const float* __restrict__ pred1_w,
                            const float* __restrict__ pred1_b,
                            float* __restrict__ out) {
    int idx = blockIdx.x * blockDim.x + threadIdx.x;
    if (idx >= NQ * 4) return;
    int q = idx / 4, o = idx % 4;
    float s = pred1_b[o];
    #pragma unroll 4
    for (int k = 0; k < 192; k++)
        s += g_T[q * 192 + k] * pred1_w[k * 4 + o];
    out[idx] = s;
}

// ---------------- launch ----------------
extern "C" void kernel_launch(void* const* d_in, const int* in_sizes, int n_in,
                              void* d_out, int out_size) {
    const float* x        = (const float*)d_in[0];
    const float* qpos     = (const float*)d_in[1];
    const int*   edges    = (const int*)d_in[2];    // int32 (JAX x64 disabled)
    const float* proj_w   = (const float*)d_in[3];
    const float* proj_b   = (const float*)d_in[4];
    const float* msg0_w   = (const float*)d_in[5];
    const float* msg0_b   = (const float*)d_in[6];
    const float* msg1_w   = (const float*)d_in[7];
    const float* msg1_b   = (const float*)d_in[8];
    const float* msg2_w   = (const float*)d_in[9];
    const float* msg2_b   = (const float*)d_in[10];
    const float* pred0_w  = (const float*)d_in[11];
    const float* pred0_b  = (const float*)d_in[12];
    const float* pred1_w  = (const float*)d_in[13];
    const float* pred1_b  = (const float*)d_in[14];
    float*       out      = (float*)d_out;

    float *pWc, *pbc, *pQE, *pA1, *pA2, *pH0, *pH1, *pM, *pT;
    cudaGetSymbolAddress((void**)&pWc, g_Wc);
    cudaGetSymbolAddress((void**)&pbc, g_bc);
    cudaGetSymbolAddress((void**)&pQE, g_QE);
    cudaGetSymbolAddress((void**)&pA1, g_A1);
    cudaGetSymbolAddress((void**)&pA2, g_A2);
    cudaGetSymbolAddress((void**)&pH0, g_H0);
    cudaGetSymbolAddress((void**)&pH1, g_H1);
    cudaGetSymbolAddress((void**)&pM,  g_M);
    cudaGetSymbolAddress((void**)&pT,  g_T);
    float* pH2 = pH0;   // H0 is dead after the msg1 GEMM; reuse for H2

    // 1) fold proj into msg0_top: Wc[192,384], bc[384]
    fold_w_kernel<<<(192 * 384 + 255) / 256, 256>>>(proj_w, msg0_w);
    fold_b_kernel<<<2, 192>>>(proj_b, msg0_w, msg0_b);

    // 2) sincos embedding
    qe_kernel<<<(NQ * 192 + 255) / 256, 256>>>(qpos);

    // 3) A1 = x @ Wc + bc   [32768, 384]
    {
        dim3 grid(3, S / 128);
        sgemm_kernel<false><<<grid, 256>>>(x, pWc, pbc, pA1, S, 384, 192);
    }
    // 4) A2 = QE @ msg0_w_bot   [32768, 384]
    {
        dim3 grid(3, NQ / 128);
        sgemm_kernel<false><<<grid, 256>>>(pQE, msg0_w + 192 * 384, nullptr, pA2, NQ, 384, 192);
    }
    // 5) H0 = gelu(A1[g] + A2[q])  [NE, 384]
    edge0_kernel<<<(int)(((long long)NE * 384 + 255) / 256), 256>>>(edges);

    // 6) H1 = gelu(H0 @ msg1_w + b1)  [NE, 384]
    {
        dim3 grid(3, NE / 128);
        sgemm_kernel<true><<<grid, 256>>>(pH0, msg1_w, msg1_b, pH1, NE, 384, 384);
    }
    // 7) H2 = H1 @ msg2_w + b2  [NE, 192]  (into reused H0 buffer)
    {
        dim3 grid(2, NE / 128);
        sgemm_kernel<false><<<grid, 256>>>(pH1, msg2_w, msg2_b, pH2, NE, 192, 384);
    }
    // 8) segment offsets + mean
    segstart_kernel<<<(NQ + 1 + 255) / 256, 256>>>(edges);
    segmean_kernel<<<NQ, 192>>>(pH2);

    // 9) T = gelu(M @ pred0_w + pred0_b)  [NQ, 192]
    {
        dim3 grid(2, NQ / 128);
        sgemm_kernel<true><<<grid, 256>>>(pM, pred0_w, pred0_b, pT, NQ, 192, 192);
    }
    // 10) out = T @ pred1_w + pred1_b  [NQ, 4]
    outk_kernel<<<(NQ * 4 + 127) / 128, 128>>>(pred1_w, pred1_b, out);
}

// round 4
// speedup vs baseline: 3.3808x; 3.3808x over previous
#include <cuda_runtime.h>
#include <cuda_bf16.h>
#include <math.h>
#include <stdint.h>

// ---------------- problem constants ----------------
#define NQ   32768
#define NE   262144
#define S    32768

// ---------------- scratch (device globals; 16B aligned) ----------------
__device__ __align__(16) float g_Wc[192 * 384];          // proj_w @ msg0_w_top
__device__ __align__(16) float g_bc[384];                // proj_b @ msg0_w_top + msg0_b
__device__ __align__(16) float g_QE[NQ * 192];           // sincos embed
__device__ __align__(16) float g_A1[S * 384];            // x @ Wc + bc
__device__ __align__(16) float g_A2[NQ * 384];           // QE @ msg0_w_bot
__device__ __align__(16) float g_H0[(size_t)NE * 384];   // gelu(A1[g]+A2[q]); reused for H2
__device__ __align__(16) float g_H1[(size_t)NE * 384];   // gelu(H0 @ msg1 + b1)
__device__ __align__(16) float g_M [NQ * 192];           // segment mean
__device__ __align__(16) float g_T [NQ * 192];           // gelu(M @ pred0 + b)
__device__ int   g_start[NQ + 1];                        // segment offsets (qidx sorted)

__device__ __forceinline__ float gelu_f(float x) {
    return 0.5f * x * (1.0f + erff(x * 0.70710678118654752f));
}

__device__ __forceinline__ uint32_t f2tf(float x) {
    uint32_t r;
    asm("cvt.rna.tf32.f32 %0, %1;" : "=r"(r) : "f"(x));
    return r;
}

// ---------------- weight folding ----------------
__global__ void fold_w_kernel(const float* __restrict__ proj_w,
                              const float* __restrict__ msg0_w) {
    int idx = blockIdx.x * blockDim.x + threadIdx.x;
    if (idx >= 192 * 384) return;
    int i = idx / 384, n = idx % 384;
    float s = 0.f;
    #pragma unroll 4
    for (int j = 0; j < 192; j++)
        s += proj_w[i * 192 + j] * msg0_w[j * 384 + n];
    g_Wc[idx] = s;
}

__global__ void fold_b_kernel(const float* __restrict__ proj_b,
                              const float* __restrict__ msg0_w,
                              const float* __restrict__ msg0_b) {
    int n = blockIdx.x * blockDim.x + threadIdx.x;
    if (n >= 384) return;
    float s = msg0_b[n];
    #pragma unroll 4
    for (int j = 0; j < 192; j++)
        s += proj_b[j] * msg0_w[j * 384 + n];
    g_bc[n] = s;
}

// ---------------- sincos positional embedding ----------------
__global__ void qe_kernel(const float* __restrict__ query_pos) {
    int idx = blockIdx.x * blockDim.x + threadIdx.x;
    if (idx >= NQ * 192) return;
    int q = idx / 192, c = idx % 192;
    int d = c / 64, j = c % 64;
    int i = (j < 32) ? j : j - 32;
    float coord = query_pos[q * 3 + d];
    float expo  = (2.0f * (float)i) / 64.0f;
    float omega = powf(10000.0f, -expo);
    float a = coord * omega;
    g_QE[idx] = (j < 32) ? sinf(a) : cosf(a);
}

// ---------------- tf32 tensor-core GEMM ----------------
// C[M,N] = op(A[M,K] @ B[K,N] + bias). 128x128 tile, BK=16.
// 256 threads = 8 warps; warp tile 32(M) x 64(N) = 2 mfrag x 8 nfrag of m16n8k8.
// Requires: M % 128 == 0, K % 16 == 0, N % 4 == 0 (N-edge guarded).
template <bool GELU>
__global__ __launch_bounds__(256, 2)
void tf32gemm_kernel(const float* __restrict__ A, const float* __restrict__ B,
                     const float* __restrict__ bias, float* __restrict__ C,
                     int M, int N, int K) {
    __shared__ uint32_t As[128][20];   // [m][k], pad 4 -> stride 20 (conflict-free frag loads)
    __shared__ uint32_t Bs[16][132];   // [k][n], pad 4 -> stride 132

    const int tid  = threadIdx.x;
    const int lane = tid & 31;
    const int warp = tid >> 5;
    const int gid  = lane >> 2;     // 0..7
    const int tig  = lane & 3;      // 0..3
    const int wm   = (warp & 3) * 32;
    const int wn   = (warp >> 2) * 64;
    const int bm   = blockIdx.y * 128;
    const int bn   = blockIdx.x * 128;

    float acc[2][8][4];
    #pragma unroll
    for (int mf = 0; mf < 2; mf++)
        #pragma unroll
        for (int nf = 0; nf < 8; nf++)
            #pragma unroll
            for (int i = 0; i < 4; i++) acc[mf][nf][i] = 0.f;

    // A loader: thread covers row tid>>1, float4 slots ac4, ac4+1
    const int arow = tid >> 1;
    const int ac4  = (tid & 1) * 2;
    // B loader: float4 id f = tid*2 -> row f>>5, col4 f&31
    const int bkr  = (tid * 2) >> 5;
    const int bn4  = (tid * 2) & 31;

    for (int kt = 0; kt < K; kt += 16) {
        // --- load A 128x16 ---
        {
            const float4* Ap = (const float4*)(A + (size_t)(bm + arow) * K + kt);
            float4 av0 = Ap[ac4];
            float4 av1 = Ap[ac4 + 1];
            int k0 = ac4 * 4;
            As[arow][k0 + 0] = f2tf(av0.x);
            As[arow][k0 + 1] = f2tf(av0.y);
            As[arow][k0 + 2] = f2tf(av0.z);
            As[arow][k0 + 3] = f2tf(av0.w);
            As[arow][k0 + 4] = f2tf(av1.x);
            As[arow][k0 + 5] = f2tf(av1.y);
            As[arow][k0 + 6] = f2tf(av1.z);
            As[arow][k0 + 7] = f2tf(av1.w);
        }
        // --- load B 16x128 (N-edge guarded) ---
        {
            const float* Brow = B + (size_t)(kt + bkr) * N;
            int c0 = bn + bn4 * 4;
            int c1 = bn + (bn4 + 1) * 4;
            float4 bv0 = (c0 < N) ? *(const float4*)(Brow + c0) : make_float4(0.f,0.f,0.f,0.f);
            float4 bv1 = (c1 < N) ? *(const float4*)(Brow + c1) : make_float4(0.f,0.f,0.f,0.f);
            Bs[bkr][bn4 * 4 + 0] = f2tf(bv0.x);
            Bs[bkr][bn4 * 4 + 1] = f2tf(bv0.y);
            Bs[bkr][bn4 * 4 + 2] = f2tf(bv0.z);
            Bs[bkr][bn4 * 4 + 3] = f2tf(bv0.w);
            Bs[bkr][bn4 * 4 + 4] = f2tf(bv1.x);
            Bs[bkr][bn4 * 4 + 5] = f2tf(bv1.y);
            Bs[bkr][bn4 * 4 + 6] = f2tf(bv1.z);
            Bs[bkr][bn4 * 4 + 7] = f2tf(bv1.w);
        }
        __syncthreads();

        #pragma unroll
        for (int ks = 0; ks < 2; ks++) {
            const int k0 = ks * 8;
            uint32_t a[2][4];
            #pragma unroll
            for (int mf = 0; mf < 2; mf++) {
                int m = wm + mf * 16 + gid;
                a[mf][0] = As[m    ][k0 + tig];
                a[mf][1] = As[m + 8][k0 + tig];
                a[mf][2] = As[m    ][k0 + tig + 4];
                a[mf][3] = As[m + 8][k0 + tig + 4];
            }
            uint32_t b[8][2];
            #pragma unroll
            for (int nf = 0; nf < 8; nf++) {
                int n = wn + nf * 8 + gid;
                b[nf][0] = Bs[k0 + tig    ][n];
                b[nf][1] = Bs[k0 + tig + 4][n];
            }
            #pragma unroll
            for (int mf = 0; mf < 2; mf++)
                #pragma unroll
                for (int nf = 0; nf < 8; nf++) {
                    asm volatile(
                        "mma.sync.aligned.m16n8k8.row.col.f32.tf32.tf32.f32 "
                        "{%0,%1,%2,%3}, {%4,%5,%6,%7}, {%8,%9}, {%0,%1,%2,%3};"
                        : "+f"(acc[mf][nf][0]), "+f"(acc[mf][nf][1]),
                          "+f"(acc[mf][nf][2]), "+f"(acc[mf][nf][3])
                        : "r"(a[mf][0]), "r"(a[mf][1]), "r"(a[mf][2]), "r"(a[mf][3]),
                          "r"(b[nf][0]), "r"(b[nf][1]));
                }
        }
        __syncthreads();
    }

    // --- epilogue ---
    #pragma unroll
    for (int mf = 0; mf < 2; mf++) {
        int row0 = bm + wm + mf * 16 + gid;
        int row1 = row0 + 8;
        #pragma unroll
        for (int nf = 0; nf < 8; nf++) {
            int col = bn + wn + nf * 8 + tig * 2;
            if (col < N) {
                float bb0 = bias ? bias[col]     : 0.f;
                float bb1 = bias ? bias[col + 1] : 0.f;
                float v00 = acc[mf][nf][0] + bb0;
                float v01 = acc[mf][nf][1] + bb1;
                float v10 = acc[mf][nf][2] + bb0;
                float v11 = acc[mf][nf][3] + bb1;
                if (GELU) {
                    v00 = gelu_f(v00); v01 = gelu_f(v01);
                    v10 = gelu_f(v10); v11 = gelu_f(v11);
                }
                *(float2*)&C[(size_t)row0 * N + col] = make_float2(v00, v01);
                *(float2*)&C[(size_t)row1 * N + col] = make_float2(v10, v11);
            }
        }
    }
}

// ---------------- edge layer 0: H0[e] = gelu(A1[g[e]] + A2[q[e]]) ----------------
__global__ void edge0_kernel(const int* __restrict__ edges) {
    int idx = blockIdx.x * blockDim.x + threadIdx.x;   // over NE*96 float4s
    if (idx >= NE * 96) return;
    int e = idx / 96, c4 = idx % 96;
    int q = __ldg(&edges[2 * e]);
    int g = __ldg(&edges[2 * e + 1]);
    float4 a = *(const float4*)&g_A1[(size_t)g * 384 + c4 * 4];
    float4 b = *(const float4*)&g_A2[(size_t)q * 384 + c4 * 4];
    float4 o;
    o.x = gelu_f(a.x + b.x);
    o.y = gelu_f(a.y + b.y);
    o.z = gelu_f(a.z + b.z);
    o.w = gelu_f(a.w + b.w);
    *(float4*)&g_H0[(size_t)e * 384 + c4 * 4] = o;
}

// ---------------- segment offsets (qidx sorted ascending) ----------------
__global__ void segstart_kernel(const int* __restrict__ edges) {
    int q = blockIdx.x * blockDim.x + threadIdx.x;
    if (q > NQ) return;
    if (q == NQ) { g_start[NQ] = NE; return; }
    int lo = 0, hi = NE;
    while (lo < hi) {
        int mid = (lo + hi) >> 1;
        int v = edges[2 * mid];
        if (v < q) lo = mid + 1; else hi = mid;
    }
    g_start[q] = lo;
}

// ---------------- segment mean over H2 ----------------
__global__ void segmean_kernel(const float* __restrict__ H2) {
    int q = blockIdx.x;
    int c = threadIdx.x;   // 0..191
    int s = g_start[q], e = g_start[q + 1];
    float sum = 0.f;
    for (int i = s; i < e; i++)
        sum += H2[(size_t)i * 192 + c];
    float cnt = (float)(e - s);
    g_M[q * 192 + c] = sum / fmaxf(cnt, 1.0f);
}

// ---------------- final tiny projection ----------------
__global__ void outk_kernel(const float* __restrict__ pred1_w,
                            const float* __restrict__ pred1_b,
                            float* __restrict__ out) {
    int idx = blockIdx.x * blockDim.x + threadIdx.x;
    if (idx >= NQ * 4) return;
    int q = idx / 4, o = idx % 4;
    float s = pred1_b[o];
    #pragma unroll 4
    for (int k = 0; k < 192; k++)
        s += g_T[q * 192 + k] * pred1_w[k * 4 + o];
    out[idx] = s;
}

// ---------------- launch ----------------
extern "C" void kernel_launch(void* const* d_in, const int* in_sizes, int n_in,
                              void* d_out, int out_size) {
    const float* x        = (const float*)d_in[0];
    const float* qpos     = (const float*)d_in[1];
    const int*   edges    = (const int*)d_in[2];    // int32 (JAX x64 disabled)
    const float* proj_w   = (const float*)d_in[3];
    const float* proj_b   = (const float*)d_in[4];
    const float* msg0_w   = (const float*)d_in[5];
    const float* msg0_b   = (const float*)d_in[6];
    const float* msg1_w   = (const float*)d_in[7];
    const float* msg1_b   = (const float*)d_in[8];
    const float* msg2_w   = (const float*)d_in[9];
    const float* msg2_b   = (const float*)d_in[10];
    const float* pred0_w  = (const float*)d_in[11];
    const float* pred0_b  = (const float*)d_in[12];
    const float* pred1_w  = (const float*)d_in[13];
    const float* pred1_b  = (const float*)d_in[14];
    float*       out      = (float*)d_out;

    float *pWc, *pbc, *pQE, *pA1, *pA2, *pH0, *pH1, *pM, *pT;
    cudaGetSymbolAddress((void**)&pWc, g_Wc);
    cudaGetSymbolAddress((void**)&pbc, g_bc);
    cudaGetSymbolAddress((void**)&pQE, g_QE);
    cudaGetSymbolAddress((void**)&pA1, g_A1);
    cudaGetSymbolAddress((void**)&pA2, g_A2);
    cudaGetSymbolAddress((void**)&pH0, g_H0);
    cudaGetSymbolAddress((void**)&pH1, g_H1);
    cudaGetSymbolAddress((void**)&pM,  g_M);
    cudaGetSymbolAddress((void**)&pT,  g_T);
    float* pH2 = pH0;   // H0 dead after msg1 GEMM; reuse for H2

    // 1) fold proj into msg0_top
    fold_w_kernel<<<(192 * 384 + 255) / 256, 256>>>(proj_w, msg0_w);
    fold_b_kernel<<<2, 192>>>(proj_b, msg0_w, msg0_b);

    // 2) sincos embedding
    qe_kernel<<<(NQ * 192 + 255) / 256, 256>>>(qpos);

    // 3) A1 = x @ Wc + bc   [S, 384]
    tf32gemm_kernel<false><<<dim3(3, S / 128), 256>>>(x, pWc, pbc, pA1, S, 384, 192);

    // 4) A2 = QE @ msg0_w_bot   [NQ, 384]
    tf32gemm_kernel<false><<<dim3(3, NQ / 128), 256>>>(pQE, msg0_w + 192 * 384, nullptr, pA2, NQ, 384, 192);

    // 5) H0 = gelu(A1[g] + A2[q])  [NE, 384]
    edge0_kernel<<<(NE * 96 + 255) / 256, 256>>>(edges);

    // 6) H1 = gelu(H0 @ msg1_w + b1)  [NE, 384]
    tf32gemm_kernel<true><<<dim3(3, NE / 128), 256>>>(pH0, msg1_w, msg1_b, pH1, NE, 384, 384);

    // 7) H2 = H1 @ msg2_w + b2  [NE, 192]  (into reused H0 buffer)
    tf32gemm_kernel<false><<<dim3(2, NE / 128), 256>>>(pH1, msg2_w, msg2_b, pH2, NE, 192, 384);

    // 8) segment offsets + mean
    segstart_kernel<<<(NQ + 1 + 255) / 256, 256>>>(edges);
    segmean_kernel<<<NQ, 192>>>(pH2);

    // 9) T = gelu(M @ pred0_w + pred0_b)  [NQ, 192]
    tf32gemm_kernel<true><<<dim3(2, NQ / 128), 256>>>(pM, pred0_w, pred0_b, pT, NQ, 192, 192);

    // 10) out = T @ pred1_w + pred1_b  [NQ, 4]
    outk_kernel<<<(NQ * 4 + 127) / 128, 128>>>(pred1_w, pred1_b, out);
}

// round 5
// speedup vs baseline: 3.4688x; 1.0260x over previous
#include <cuda_runtime.h>
#include <cuda_bf16.h>
#include <math.h>
#include <stdint.h>

// ---------------- problem constants ----------------
#define NQ   32768
#define NE   262144
#define S    32768

// ---------------- scratch (device globals; 16B aligned) ----------------
__device__ __align__(16) float g_Wc[192 * 384];          // proj_w @ msg0_w_top
__device__ __align__(16) float g_bc[384];                // proj_b @ msg0_w_top + msg0_b
__device__ __align__(16) float g_QE[NQ * 192];           // sincos embed
__device__ __align__(16) float g_A1[S * 384];            // x @ Wc + bc
__device__ __align__(16) float g_A2[NQ * 384];           // QE @ msg0_w_bot
__device__ __align__(16) float g_H0[(size_t)NE * 384];   // gelu(A1[g]+A2[q]); reused for H2
__device__ __align__(16) float g_H1[(size_t)NE * 384];   // gelu(H0 @ msg1 + b1)
__device__ __align__(16) float g_M [NQ * 192];           // segment mean
__device__ __align__(16) float g_T [NQ * 192];           // gelu(M @ pred0 + b)
__device__ int   g_start[NQ + 1];                        // segment offsets (qidx sorted)

__device__ __forceinline__ float gelu_f(float x) {
    return 0.5f * x * (1.0f + erff(x * 0.70710678118654752f));
}

__device__ __forceinline__ uint32_t f2tf(float x) {
    uint32_t r;
    asm("cvt.rna.tf32.f32 %0, %1;" : "=r"(r) : "f"(x));
    return r;
}

// ---------------- weight folding ----------------
__global__ void fold_w_kernel(const float* __restrict__ proj_w,
                              const float* __restrict__ msg0_w) {
    int idx = blockIdx.x * blockDim.x + threadIdx.x;
    if (idx >= 192 * 384) return;
    int i = idx / 384, n = idx % 384;
    float s = 0.f;
    #pragma unroll 4
    for (int j = 0; j < 192; j++)
        s += proj_w[i * 192 + j] * msg0_w[j * 384 + n];
    g_Wc[idx] = s;
}

__global__ void fold_b_kernel(const float* __restrict__ proj_b,
                              const float* __restrict__ msg0_w,
                              const float* __restrict__ msg0_b) {
    int n = blockIdx.x * blockDim.x + threadIdx.x;
    if (n >= 384) return;
    float s = msg0_b[n];
    #pragma unroll 4
    for (int j = 0; j < 192; j++)
        s += proj_b[j] * msg0_w[j * 384 + n];
    g_bc[n] = s;
}

// ---------------- sincos positional embedding ----------------
__global__ void qe_kernel(const float* __restrict__ query_pos) {
    int idx = blockIdx.x * blockDim.x + threadIdx.x;
    if (idx >= NQ * 192) return;
    int q = idx / 192, c = idx % 192;
    int d = c / 64, j = c % 64;
    int i = (j < 32) ? j : j - 32;
    float coord = query_pos[q * 3 + d];
    float expo  = (2.0f * (float)i) / 64.0f;
    float omega = powf(10000.0f, -expo);
    float a = coord * omega;
    g_QE[idx] = (j < 32) ? sinf(a) : cosf(a);
}

// ---------------- tf32 tensor-core GEMM, pair-packed smem + double buffer ----------------
// C[M,N] = op(A[M,K] @ B[K,N] + bias). 128x128 tile, BK=16, 8 warps, warp tile 32x64.
// Smem layout: k-groups of 8 permuted as [k0,k4,k1,k5,k2,k6,k3,k7] so mma pairs
// (tig, tig+4) are LDS.64. Row stride 24 words (conflict-free frag loads).
// Requires: M % 128 == 0, K % 16 == 0, N % 4 == 0 (N-edge guarded).
template <bool GELU>
__global__ __launch_bounds__(256, 2)
void tf32gemm_kernel(const float* __restrict__ A, const float* __restrict__ B,
                     const float* __restrict__ bias, float* __restrict__ C,
                     int M, int N, int K) {
    __shared__ uint32_t As[2][128][24];   // [buf][m][kpos], 24KB
    __shared__ uint32_t Bs[2][128][24];   // [buf][n][kpos], 24KB

    const int tid  = threadIdx.x;
    const int lane = tid & 31;
    const int warp = tid >> 5;
    const int gid  = lane >> 2;     // 0..7
    const int tig  = lane & 3;      // 0..3
    const int wm   = (warp & 3) * 32;
    const int wn   = (warp >> 2) * 64;
    const int bm   = blockIdx.y * 128;
    const int bn   = blockIdx.x * 128;

    float acc[2][8][4];
    #pragma unroll
    for (int mf = 0; mf < 2; mf++)
        #pragma unroll
        for (int nf = 0; nf < 8; nf++)
            #pragma unroll
            for (int i = 0; i < 4; i++) acc[mf][nf][i] = 0.f;

    // A loader: thread -> row ar (0..127), k-half ah (0 or 8)
    const int ar = tid >> 1;
    const int ah = (tid & 1) * 8;
    const float* Aptr = A + (size_t)(bm + ar) * K + ah;
    // B loader: thread -> k-row bk (0..15), n-chunk bn0 (0..120 step 8)
    const int bk  = tid & 15;
    const int bn0 = (tid >> 4) * 8;
    const int bkpos = ((bk >> 3) * 8) + ((bk & 3) * 2) + ((bk >> 2) & 1);
    const int bc0 = bn + bn0;

    float4 av0, av1, bv0, bv1;

    // ---- prologue: load tile 0 ----
    av0 = *(const float4*)(Aptr + 0);
    av1 = *(const float4*)(Aptr + 4);
    {
        const float* Brow = B + (size_t)bk * N;
        bv0 = (bc0     < N) ? *(const float4*)(Brow + bc0)     : make_float4(0,0,0,0);
        bv1 = (bc0 + 4 < N) ? *(const float4*)(Brow + bc0 + 4) : make_float4(0,0,0,0);
    }
    {
        uint32_t* aw = &As[0][ar][ah];
        uint4 w0 = make_uint4(f2tf(av0.x), f2tf(av1.x), f2tf(av0.y), f2tf(av1.y));
        uint4 w1 = make_uint4(f2tf(av0.z), f2tf(av1.z), f2tf(av0.w), f2tf(av1.w));
        *(uint4*)(aw)     = w0;
        *(uint4*)(aw + 4) = w1;
        Bs[0][bn0 + 0][bkpos] = f2tf(bv0.x);
        Bs[0][bn0 + 1][bkpos] = f2tf(bv0.y);
        Bs[0][bn0 + 2][bkpos] = f2tf(bv0.z);
        Bs[0][bn0 + 3][bkpos] = f2tf(bv0.w);
        Bs[0][bn0 + 4][bkpos] = f2tf(bv1.x);
        Bs[0][bn0 + 5][bkpos] = f2tf(bv1.y);
        Bs[0][bn0 + 6][bkpos] = f2tf(bv1.z);
        Bs[0][bn0 + 7][bkpos] = f2tf(bv1.w);
    }
    __syncthreads();

    int buf = 0;
    for (int kt = 0; kt < K; kt += 16) {
        const bool haveNext = (kt + 16 < K);
        // ---- prefetch next tile into registers (in flight during MMAs) ----
        if (haveNext) {
            av0 = *(const float4*)(Aptr + kt + 16);
            av1 = *(const float4*)(Aptr + kt + 20);
            const float* Brow = B + (size_t)(kt + 16 + bk) * N;
            bv0 = (bc0     < N) ? *(const float4*)(Brow + bc0)     : make_float4(0,0,0,0);
            bv1 = (bc0 + 4 < N) ? *(const float4*)(Brow + bc0 + 4) : make_float4(0,0,0,0);
        }
        // ---- compute current tile ----
        #pragma unroll
        for (int ks = 0; ks < 2; ks++) {
            const int k8 = ks * 8;
            uint32_t a[2][4];
            #pragma unroll
            for (int mf = 0; mf < 2; mf++) {
                const int m = wm + mf * 16;
                uint2 plo = *(const uint2*)&As[buf][m + gid    ][k8 + tig * 2];
                uint2 phi = *(const uint2*)&As[buf][m + gid + 8][k8 + tig * 2];
                a[mf][0] = plo.x;   // A[gid][tig]
                a[mf][1] = phi.x;   // A[gid+8][tig]
                a[mf][2] = plo.y;   // A[gid][tig+4]
                a[mf][3] = phi.y;   // A[gid+8][tig+4]
            }
            uint32_t b[8][2];
            #pragma unroll
            for (int nf = 0; nf < 8; nf++) {
                uint2 q = *(const uint2*)&Bs[buf][wn + nf * 8 + gid][k8 + tig * 2];
                b[nf][0] = q.x;     // B[k0+tig][n]
                b[nf][1] = q.y;     // B[k0+tig+4][n]
            }
            #pragma unroll
            for (int mf = 0; mf < 2; mf++)
                #pragma unroll
                for (int nf = 0; nf < 8; nf++) {
                    asm volatile(
                        "mma.sync.aligned.m16n8k8.row.col.f32.tf32.tf32.f32 "
                        "{%0,%1,%2,%3}, {%4,%5,%6,%7}, {%8,%9}, {%0,%1,%2,%3};"
                        : "+f"(acc[mf][nf][0]), "+f"(acc[mf][nf][1]),
                          "+f"(acc[mf][nf][2]), "+f"(acc[mf][nf][3])
                        : "r"(a[mf][0]), "r"(a[mf][1]), "r"(a[mf][2]), "r"(a[mf][3]),
                          "r"(b[nf][0]), "r"(b[nf][1]));
                }
        }
        // ---- store next tile into the other buffer ----
        if (haveNext) {
            const int nb = buf ^ 1;
            uint32_t* aw = &As[nb][ar][ah];
            uint4 w0 = make_uint4(f2tf(av0.x), f2tf(av1.x), f2tf(av0.y), f2tf(av1.y));
            uint4 w1 = make_uint4(f2tf(av0.z), f2tf(av1.z), f2tf(av0.w), f2tf(av1.w));
            *(uint4*)(aw)     = w0;
            *(uint4*)(aw + 4) = w1;
            Bs[nb][bn0 + 0][bkpos] = f2tf(bv0.x);
            Bs[nb][bn0 + 1][bkpos] = f2tf(bv0.y);
            Bs[nb][bn0 + 2][bkpos] = f2tf(bv0.z);
            Bs[nb][bn0 + 3][bkpos] = f2tf(bv0.w);
            Bs[nb][bn0 + 4][bkpos] = f2tf(bv1.x);
            Bs[nb][bn0 + 5][bkpos] = f2tf(bv1.y);
            Bs[nb][bn0 + 6][bkpos] = f2tf(bv1.z);
            Bs[nb][bn0 + 7][bkpos] = f2tf(bv1.w);
            __syncthreads();
            buf = nb;
        }
    }

    // ---- epilogue ----
    #pragma unroll
    for (int mf = 0; mf < 2; mf++) {
        int row0 = bm + wm + mf * 16 + gid;
        int row1 = row0 + 8;
        #pragma unroll
        for (int nf = 0; nf < 8; nf++) {
            int col = bn + wn + nf * 8 + tig * 2;
            if (col < N) {
                float bb0 = bias ? bias[col]     : 0.f;
                float bb1 = bias ? bias[col + 1] : 0.f;
                float v00 = acc[mf][nf][0] + bb0;
                float v01 = acc[mf][nf][1] + bb1;
                float v10 = acc[mf][nf][2] + bb0;
                float v11 = acc[mf][nf][3] + bb1;
                if (GELU) {
                    v00 = gelu_f(v00); v01 = gelu_f(v01);
                    v10 = gelu_f(v10); v11 = gelu_f(v11);
                }
                *(float2*)&C[(size_t)row0 * N + col] = make_float2(v00, v01);
                *(float2*)&C[(size_t)row1 * N + col] = make_float2(v10, v11);
            }
        }
    }
}

// ---------------- edge layer 0: H0[e] = gelu(A1[g[e]] + A2[q[e]]) ----------------
__global__ void edge0_kernel(const int* __restrict__ edges) {
    int idx = blockIdx.x * blockDim.x + threadIdx.x;   // over NE*96 float4s
    if (idx >= NE * 96) return;
    int e = idx / 96, c4 = idx % 96;
    int q = __ldg(&edges[2 * e]);
    int g = __ldg(&edges[2 * e + 1]);
    float4 a = *(const float4*)&g_A1[(size_t)g * 384 + c4 * 4];
    float4 b = *(const float4*)&g_A2[(size_t)q * 384 + c4 * 4];
    float4 o;
    o.x = gelu_f(a.x + b.x);
    o.y = gelu_f(a.y + b.y);
    o.z = gelu_f(a.z + b.z);
    o.w = gelu_f(a.w + b.w);
    *(float4*)&g_H0[(size_t)e * 384 + c4 * 4] = o;
}

// ---------------- segment offsets (qidx sorted ascending) ----------------
__global__ void segstart_kernel(const int* __restrict__ edges) {
    int q = blockIdx.x * blockDim.x + threadIdx.x;
    if (q > NQ) return;
    if (q == NQ) { g_start[NQ] = NE; return; }
    int lo = 0, hi = NE;
    while (lo < hi) {
        int mid = (lo + hi) >> 1;
        int v = edges[2 * mid];
        if (v < q) lo = mid + 1; else hi = mid;
    }
    g_start[q] = lo;
}

// ---------------- segment mean over H2 ----------------
__global__ void segmean_kernel(const float* __restrict__ H2) {
    int q = blockIdx.x;
    int c = threadIdx.x;   // 0..191
    int s = g_start[q], e = g_start[q + 1];
    float sum = 0.f;
    for (int i = s; i < e; i++)
        sum += H2[(size_t)i * 192 + c];
    float cnt = (float)(e - s);
    g_M[q * 192 + c] = sum / fmaxf(cnt, 1.0f);
}

// ---------------- final tiny projection ----------------
__global__ void outk_kernel(const float* __restrict__ pred1_w,
                            const float* __restrict__ pred1_b,
                            float* __restrict__ out) {
    int idx = blockIdx.x * blockDim.x + threadIdx.x;
    if (idx >= NQ * 4) return;
    int q = idx / 4, o = idx % 4;
    float s = pred1_b[o];
    #pragma unroll 4
    for (int k = 0; k < 192; k++)
        s += g_T[q * 192 + k] * pred1_w[k * 4 + o];
    out[idx] = s;
}

// ---------------- launch ----------------
extern "C" void kernel_launch(void* const* d_in, const int* in_sizes, int n_in,
                              void* d_out, int out_size) {
    const float* x        = (const float*)d_in[0];
    const float* qpos     = (const float*)d_in[1];
    const int*   edges    = (const int*)d_in[2];    // int32 (JAX x64 disabled)
    const float* proj_w   = (const float*)d_in[3];
    const float* proj_b   = (const float*)d_in[4];
    const float* msg0_w   = (const float*)d_in[5];
    const float* msg0_b   = (const float*)d_in[6];
    const float* msg1_w   = (const float*)d_in[7];
    const float* msg1_b   = (const float*)d_in[8];
    const float* msg2_w   = (const float*)d_in[9];
    const float* msg2_b   = (const float*)d_in[10];
    const float* pred0_w  = (const float*)d_in[11];
    const float* pred0_b  = (const float*)d_in[12];
    const float* pred1_w  = (const float*)d_in[13];
    const float* pred1_b  = (const float*)d_in[14];
    float*       out      = (float*)d_out;

    float *pWc, *pbc, *pQE, *pA1, *pA2, *pH0, *pH1, *pM, *pT;
    cudaGetSymbolAddress((void**)&pWc, g_Wc);
    cudaGetSymbolAddress((void**)&pbc, g_bc);
    cudaGetSymbolAddress((void**)&pQE, g_QE);
    cudaGetSymbolAddress((void**)&pA1, g_A1);
    cudaGetSymbolAddress((void**)&pA2, g_A2);
    cudaGetSymbolAddress((void**)&pH0, g_H0);
    cudaGetSymbolAddress((void**)&pH1, g_H1);
    cudaGetSymbolAddress((void**)&pM,  g_M);
    cudaGetSymbolAddress((void**)&pT,  g_T);
    float* pH2 = pH0;   // H0 dead after msg1 GEMM; reuse for H2

    // 1) fold proj into msg0_top
    fold_w_kernel<<<(192 * 384 + 255) / 256, 256>>>(proj_w, msg0_w);
    fold_b_kernel<<<2, 192>>>(proj_b, msg0_w, msg0_b);

    // 2) sincos embedding
    qe_kernel<<<(NQ * 192 + 255) / 256, 256>>>(qpos);

    // 3) A1 = x @ Wc + bc   [S, 384]
    tf32gemm_kernel<false><<<dim3(3, S / 128), 256>>>(x, pWc, pbc, pA1, S, 384, 192);

    // 4) A2 = QE @ msg0_w_bot   [NQ, 384]
    tf32gemm_kernel<false><<<dim3(3, NQ / 128), 256>>>(pQE, msg0_w + 192 * 384, nullptr, pA2, NQ, 384, 192);

    // 5) H0 = gelu(A1[g] + A2[q])  [NE, 384]
    edge0_kernel<<<(NE * 96 + 255) / 256, 256>>>(edges);

    // 6) H1 = gelu(H0 @ msg1_w + b1)  [NE, 384]
    tf32gemm_kernel<true><<<dim3(3, NE / 128), 256>>>(pH0, msg1_w, msg1_b, pH1, NE, 384, 384);

    // 7) H2 = H1 @ msg2_w + b2  [NE, 192]  (into reused H0 buffer)
    tf32gemm_kernel<false><<<dim3(2, NE / 128), 256>>>(pH1, msg2_w, msg2_b, pH2, NE, 192, 384);

    // 8) segment offsets + mean
    segstart_kernel<<<(NQ + 1 + 255) / 256, 256>>>(edges);
    segmean_kernel<<<NQ, 192>>>(pH2);

    // 9) T = gelu(M @ pred0_w + pred0_b)  [NQ, 192]
    tf32gemm_kernel<true><<<dim3(2, NQ / 128), 256>>>(pM, pred0_w, pred0_b, pT, NQ, 192, 192);

    // 10) out = T @ pred1_w + pred1_b  [NQ, 4]
    outk_kernel<<<(NQ * 4 + 127) / 128, 128>>>(pred1_w, pred1_b, out);
}

// round 7
// speedup vs baseline: 8.3701x; 2.4130x over previous
#include <cuda_runtime.h>
#include <cuda_bf16.h>
#include <math.h>
#include <stdint.h>

// ---------------- problem constants ----------------
#define NQ   32768
#define NE   262144
#define S    32768

typedef __nv_bfloat16 bf16;

// ---------------- scratch (device globals) ----------------
__device__ __align__(16) bf16  g_WcT [384 * 192];         // (proj_w @ msg0_w_top)^T [n][k]
__device__ __align__(16) bf16  g_WbT [384 * 192];         // msg0_w_bot^T
__device__ __align__(16) bf16  g_Wt1 [384 * 384];         // msg1_w^T
__device__ __align__(16) bf16  g_Wt2 [192 * 384];         // msg2_w^T
__device__ __align__(16) bf16  g_Wp0T[192 * 192];         // pred0_w^T
__device__ __align__(16) float g_bc[384];                 // folded bias
__device__ __align__(16) bf16  g_Xh [S * 192];            // x in bf16
__device__ __align__(16) bf16  g_QEh[NQ * 192];           // sincos embed bf16
__device__ __align__(16) float g_A1[S * 384];             // x @ Wc + bc (fp32)
__device__ __align__(16) float g_A2[NQ * 384];            // QE @ msg0_w_bot (fp32)
__device__ __align__(16) bf16  g_H0h[(size_t)NE * 384];   // gelu(A1[g]+A2[q]); reused for H2
__device__ __align__(16) bf16  g_H1h[(size_t)NE * 384];   // gelu(H0 @ msg1 + b1)
__device__ __align__(16) bf16  g_Mh [NQ * 192];           // segment mean
__device__ __align__(16) float g_T  [NQ * 192];           // gelu(M @ pred0 + b) fp32
__device__ int   g_start[NQ + 1];                         // segment offsets (qidx sorted)

__device__ __forceinline__ float gelu_f(float x) {
    return 0.5f * x * (1.0f + erff(x * 0.70710678118654752f));
}

#define SWZ(o) ((o) ^ (((o) >> 3) & 0x70))

__device__ __forceinline__ uint32_t smem_u32(const void* p) {
    uint32_t a;
    asm("{ .reg .u64 t; cvta.to.shared.u64 t, %1; cvt.u32.u64 %0, t; }" : "=r"(a) : "l"(p));
    return a;
}
__device__ __forceinline__ void cp_async16(uint32_t dst, const void* src, int srcsize) {
    asm volatile("cp.async.cg.shared.global [%0], [%1], 16, %2;"
                 :: "r"(dst), "l"(src), "r"(srcsize) : "memory");
}
#define CP_COMMIT()  asm volatile("cp.async.commit_group;" ::: "memory")
#define CP_WAIT0()   asm volatile("cp.async.wait_group 0;" ::: "memory")
#define LDSM_X4(r0, r1, r2, r3, addr) \
    asm volatile("ldmatrix.sync.aligned.m8n8.x4.shared.b16 {%0,%1,%2,%3}, [%4];" \
                 : "=r"(r0), "=r"(r1), "=r"(r2), "=r"(r3) : "r"(addr))

// ---------------- bf16 tensor-core GEMM ----------------
// C[M, NT] = op(A[M, KT] @ Bt^T + bias). A bf16 row-major, Bt bf16 [NT][KT].
// 128x128 CTA tile, BK=64, cp.async double buffer, ldmatrix fragments.
// grid = (ceil(NT/128), M/128), 256 threads (8 warps, warp tile 32x64).
template <int NT, int KT, bool GELU, bool OUT_BF16>
__global__ __launch_bounds__(256)
void bf16gemm_kernel(const bf16* __restrict__ A, const bf16* __restrict__ Bt,
                     const float* __restrict__ bias, void* __restrict__ Cv) {
    constexpr int NC = KT / 64;                 // k-tiles
    extern __shared__ __align__(128) char smem_raw[];
    uint32_t sb = (smem_u32(smem_raw) + 127u) & ~127u;

    const int tid  = threadIdx.x;
    const int lane = tid & 31;
    const int warp = tid >> 5;
    const int gid  = lane >> 2;                 // 0..7
    const int tig  = lane & 3;                  // 0..3
    const int wm   = (warp & 3) * 32;
    const int wn   = (warp >> 2) * 64;
    const int bm   = blockIdx.y * 128;
    const int bn   = blockIdx.x * 128;

    float acc[2][8][4];
    #pragma unroll
    for (int mf = 0; mf < 2; mf++)
        #pragma unroll
        for (int nf = 0; nf < 8; nf++)
            #pragma unroll
            for (int i = 0; i < 4; i++) acc[mf][nf][i] = 0.f;

    // cp.async loader (A tile 128x64 bf16 = 16KB, B tile 128x64 = 16KB)
    const int lr8 = tid >> 3;        // 0..31? no: fid>>3 below
    auto load_tile = [&](int kc, int b) {
        #pragma unroll
        for (int i = 0; i < 4; i++) {
            int fid = i * 256 + tid;
            int r = fid >> 3, c = fid & 7;
            uint32_t dst = sb + b * 16384 + SWZ(r * 128 + c * 16);
            const void* src = A + (size_t)(bm + r) * KT + kc * 64 + c * 8;
            cp_async16(dst, src, 16);
        }
        #pragma unroll
        for (int i = 0; i < 4; i++) {
            int fid = i * 256 + tid;
            int r = fid >> 3, c = fid & 7;
            int n = bn + r;
            int valid = (n < NT);
            size_t nn = valid ? (size_t)n : 0;
            uint32_t dst = sb + 32768 + b * 16384 + SWZ(r * 128 + c * 16);
            const void* src = Bt + nn * KT + kc * 64 + c * 8;
            cp_async16(dst, src, valid ? 16 : 0);
        }
        CP_COMMIT();
    };

    // per-lane ldmatrix geometry
    const int q   = lane >> 3;                  // quadrant 0..3
    const int lq  = lane & 7;                   // row within quadrant
    const uint32_t swz = (uint32_t)lq << 4;
    const uint32_t kq  = (uint32_t)(q >> 1) << 4;   // 0 or 16
    const int mrow = (q & 1) * 8 + lq;
    uint32_t aoff[2], boff[4];
    #pragma unroll
    for (int mf = 0; mf < 2; mf++) aoff[mf] = (uint32_t)(wm + mf * 16 + mrow) << 7;
    #pragma unroll
    for (int p = 0; p < 4; p++)    boff[p]  = (uint32_t)(wn + p * 16 + mrow) << 7;

    load_tile(0, 0);
    int buf = 0;
    for (int c = 0; c < NC; c++) {
        CP_WAIT0();
        __syncthreads();
        if (c + 1 < NC) load_tile(c + 1, buf ^ 1);

        const uint32_t sA = sb + buf * 16384;
        const uint32_t sB = sb + 32768 + buf * 16384;
        #pragma unroll
        for (int ks = 0; ks < 4; ks++) {
            const uint32_t kxor = ((uint32_t)(ks * 32) + kq) ^ swz;
            uint32_t a[2][4];
            LDSM_X4(a[0][0], a[0][1], a[0][2], a[0][3], sA + aoff[0] + kxor);
            LDSM_X4(a[1][0], a[1][1], a[1][2], a[1][3], sA + aoff[1] + kxor);
            uint32_t b[8][2];
            #pragma unroll
            for (int p = 0; p < 4; p++) {
                uint32_t r0, r1, r2, r3;
                LDSM_X4(r0, r1, r2, r3, sB + boff[p] + kxor);
                b[2 * p][0] = r0; b[2 * p + 1][0] = r1;
                b[2 * p][1] = r2; b[2 * p + 1][1] = r3;
            }
            #pragma unroll
            for (int mf = 0; mf < 2; mf++)
                #pragma unroll
                for (int nf = 0; nf < 8; nf++) {
                    asm volatile(
                        "mma.sync.aligned.m16n8k16.row.col.f32.bf16.bf16.f32 "
                        "{%0,%1,%2,%3}, {%4,%5,%6,%7}, {%8,%9}, {%0,%1,%2,%3};"
                        : "+f"(acc[mf][nf][0]), "+f"(acc[mf][nf][1]),
                          "+f"(acc[mf][nf][2]), "+f"(acc[mf][nf][3])
                        : "r"(a[mf][0]), "r"(a[mf][1]), "r"(a[mf][2]), "r"(a[mf][3]),
                          "r"(b[nf][0]), "r"(b[nf][1]));
                }
        }
        __syncthreads();
        buf ^= 1;
    }

    // ---- epilogue: direct register -> gmem ----
    #pragma unroll
    for (int mf = 0; mf < 2; mf++) {
        int row0 = bm + wm + mf * 16 + gid;
        int row1 = row0 + 8;
        #pragma unroll
        for (int nf = 0; nf < 8; nf++) {
            int col = bn + wn + nf * 8 + tig * 2;
            if (col < NT) {
                float bb0 = bias ? bias[col]     : 0.f;
                float bb1 = bias ? bias[col + 1] : 0.f;
                float v00 = acc[mf][nf][0] + bb0;
                float v01 = acc[mf][nf][1] + bb1;
                float v10 = acc[mf][nf][2] + bb0;
                float v11 = acc[mf][nf][3] + bb1;
                if (GELU) {
                    v00 = gelu_f(v00); v01 = gelu_f(v01);
                    v10 = gelu_f(v10); v11 = gelu_f(v11);
                }
                if (OUT_BF16) {
                    bf16* C = (bf16*)Cv;
                    *(__nv_bfloat162*)&C[(size_t)row0 * NT + col] = __floats2bfloat162_rn(v00, v01);
                    *(__nv_bfloat162*)&C[(size_t)row1 * NT + col] = __floats2bfloat162_rn(v10, v11);
                } else {
                    float* C = (float*)Cv;
                    *(float2*)&C[(size_t)row0 * NT + col] = make_float2(v00, v01);
                    *(float2*)&C[(size_t)row1 * NT + col] = make_float2(v10, v11);
                }
            }
        }
    }
}

// ---------------- weight prep ----------------
__global__ void fold_w_kernel(const float* __restrict__ proj_w,
                              const float* __restrict__ msg0_w) {
    int idx = blockIdx.x * blockDim.x + threadIdx.x;
    if (idx >= 192 * 384) return;
    int i = idx / 384, n = idx % 384;
    float s = 0.f;
    #pragma unroll 4
    for (int j = 0; j < 192; j++)
        s += proj_w[i * 192 + j] * msg0_w[j * 384 + n];
    g_WcT[n * 192 + i] = __float2bfloat16_rn(s);
}
__global__ void fold_b_kernel(const float* __restrict__ proj_b,
                              const float* __restrict__ msg0_w,
                              const float* __restrict__ msg0_b) {
    int n = blockIdx.x * blockDim.x + threadIdx.x;
    if (n >= 384) return;
    float s = msg0_b[n];
    #pragma unroll 4
    for (int j = 0; j < 192; j++)
        s += proj_b[j] * msg0_w[j * 384 + n];
    g_bc[n] = s;
}
// dst[n][k] = bf16(src[k][n]), src [K][N] row-major
__global__ void transpose_bf16_kernel(const float* __restrict__ src, bf16* __restrict__ dst,
                                      int K, int N) {
    int idx = blockIdx.x * blockDim.x + threadIdx.x;
    if (idx >= K * N) return;
    int k = idx / N, n = idx % N;
    dst[n * K + k] = __float2bfloat16_rn(src[idx]);
}
// fp32 -> bf16 copy
__global__ void cvt_bf16_kernel(const float* __restrict__ src, bf16* __restrict__ dst, int n4) {
    int i = blockIdx.x * blockDim.x + threadIdx.x;
    if (i >= n4) return;
    float4 v = *(const float4*)(src + i * 4);
    __nv_bfloat162 p0 = __floats2bfloat162_rn(v.x, v.y);
    __nv_bfloat162 p1 = __floats2bfloat162_rn(v.z, v.w);
    *(uint2*)(dst + i * 4) = make_uint2(*(uint32_t*)&p0, *(uint32_t*)&p1);
}

// ---------------- sincos positional embedding (bf16 out) ----------------
__global__ void qe_kernel(const float* __restrict__ query_pos) {
    int idx = blockIdx.x * blockDim.x + threadIdx.x;
    if (idx >= NQ * 192) return;
    int qq = idx / 192, c = idx % 192;
    int d = c / 64, j = c % 64;
    int i = (j < 32) ? j : j - 32;
    float coord = query_pos[qq * 3 + d];
    float expo  = (2.0f * (float)i) / 64.0f;
    float omega = powf(10000.0f, -expo);
    float a = coord * omega;
    g_QEh[idx] = __float2bfloat16_rn((j < 32) ? sinf(a) : cosf(a));
}

// ---------------- edge layer 0: H0[e] = bf16(gelu(A1[g]+A2[q])) ----------------
__global__ void edge0_kernel(const int* __restrict__ edges) {
    int idx = blockIdx.x * blockDim.x + threadIdx.x;   // over NE*48 (8 elems each)
    if (idx >= NE * 48) return;
    int e = idx / 48, c8 = idx % 48;
    int qi = __ldg(&edges[2 * e]);
    int gi = __ldg(&edges[2 * e + 1]);
    const float* a = &g_A1[(size_t)gi * 384 + c8 * 8];
    const float* b = &g_A2[(size_t)qi * 384 + c8 * 8];
    float4 a0 = *(const float4*)(a), a1 = *(const float4*)(a + 4);
    float4 b0 = *(const float4*)(b), b1 = *(const float4*)(b + 4);
    __nv_bfloat162 p0 = __floats2bfloat162_rn(gelu_f(a0.x + b0.x), gelu_f(a0.y + b0.y));
    __nv_bfloat162 p1 = __floats2bfloat162_rn(gelu_f(a0.z + b0.z), gelu_f(a0.w + b0.w));
    __nv_bfloat162 p2 = __floats2bfloat162_rn(gelu_f(a1.x + b1.x), gelu_f(a1.y + b1.y));
    __nv_bfloat162 p3 = __floats2bfloat162_rn(gelu_f(a1.z + b1.z), gelu_f(a1.w + b1.w));
    *(uint4*)&g_H0h[(size_t)e * 384 + c8 * 8] =
        make_uint4(*(uint32_t*)&p0, *(uint32_t*)&p1, *(uint32_t*)&p2, *(uint32_t*)&p3);
}

// ---------------- segment offsets (qidx sorted ascending) ----------------
__global__ void segstart_kernel(const int* __restrict__ edges) {
    int q = blockIdx.x * blockDim.x + threadIdx.x;
    if (q > NQ) return;
    if (q == NQ) { g_start[NQ] = NE; return; }
    int lo = 0, hi = NE;
    while (lo < hi) {
        int mid = (lo + hi) >> 1;
        int v = edges[2 * mid];
        if (v < q) lo = mid + 1; else hi = mid;
    }
    g_start[q] = lo;
}

// ---------------- segment mean over H2 (bf16 in g_H0h) -> M bf16 ----------------
__global__ void segmean_kernel(const bf16* __restrict__ H2) {
    int q = blockIdx.x;
    int c = threadIdx.x;   // 0..191
    int s = g_start[q], e = g_start[q + 1];
    float sum = 0.f;
    for (int i = s; i < e; i++)
        sum += __bfloat162float(H2[(size_t)i * 192 + c]);
    float cnt = (float)(e - s);
    g_Mh[q * 192 + c] = __float2bfloat16_rn(sum / fmaxf(cnt, 1.0f));
}

// ---------------- final tiny projection ----------------
__global__ void outk_kernel(const float* __restrict__ pred1_w,
                            const float* __restrict__ pred1_b,
                            float* __restrict__ out) {
    int idx = blockIdx.x * blockDim.x + threadIdx.x;
    if (idx >= NQ * 4) return;
    int q = idx / 4, o = idx % 4;
    float s = pred1_b[o];
    #pragma unroll 4
    for (int k = 0; k < 192; k++)
        s += g_T[q * 192 + k] * pred1_w[k * 4 + o];
    out[idx] = s;
}

// ---------------- launch ----------------
static const int GEMM_SMEM = 65536 + 128;

extern "C" void kernel_launch(void* const* d_in, const int* in_sizes, int n_in,
                              void* d_out, int out_size) {
    const float* x        = (const float*)d_in[0];
    const float* qpos     = (const float*)d_in[1];
    const int*   edges    = (const int*)d_in[2];    // int32 (JAX x64 disabled)
    const float* proj_w   = (const float*)d_in[3];
    const float* proj_b   = (const float*)d_in[4];
    const float* msg0_w   = (const float*)d_in[5];
    const float* msg0_b   = (const float*)d_in[6];
    const float* msg1_w   = (const float*)d_in[7];
    const float* msg1_b   = (const float*)d_in[8];
    const float* msg2_w   = (const float*)d_in[9];
    const float* msg2_b   = (const float*)d_in[10];
    const float* pred0_w  = (const float*)d_in[11];
    const float* pred0_b  = (const float*)d_in[12];
    const float* pred1_w  = (const float*)d_in[13];
    const float* pred1_b  = (const float*)d_in[14];
    float*       out      = (float*)d_out;

    bf16 *pWcT, *pWbT, *pWt1, *pWt2, *pWp0T, *pXh, *pQEh, *pH0h, *pH1h, *pMh;
    float *pbc, *pA1, *pA2, *pT;
    cudaGetSymbolAddress((void**)&pWcT,  g_WcT);
    cudaGetSymbolAddress((void**)&pWbT,  g_WbT);
    cudaGetSymbolAddress((void**)&pWt1,  g_Wt1);
    cudaGetSymbolAddress((void**)&pWt2,  g_Wt2);
    cudaGetSymbolAddress((void**)&pWp0T, g_Wp0T);
    cudaGetSymbolAddress((void**)&pbc,   g_bc);
    cudaGetSymbolAddress((void**)&pXh,   g_Xh);
    cudaGetSymbolAddress((void**)&pQEh,  g_QEh);
    cudaGetSymbolAddress((void**)&pA1,   g_A1);
    cudaGetSymbolAddress((void**)&pA2,   g_A2);
    cudaGetSymbolAddress((void**)&pH0h,  g_H0h);
    cudaGetSymbolAddress((void**)&pH1h,  g_H1h);
    cudaGetSymbolAddress((void**)&pMh,   g_Mh);
    cudaGetSymbolAddress((void**)&pT,    g_T);
    bf16* pH2h = pH0h;   // H0 dead after msg1 GEMM; reuse for H2 (NE x 192 bf16)

    cudaFuncSetAttribute(bf16gemm_kernel<384,192,false,false>, cudaFuncAttributeMaxDynamicSharedMemorySize, GEMM_SMEM);
    cudaFuncSetAttribute(bf16gemm_kernel<384,384,true, true >, cudaFuncAttributeMaxDynamicSharedMemorySize, GEMM_SMEM);
    cudaFuncSetAttribute(bf16gemm_kernel<192,384,false,true >, cudaFuncAttributeMaxDynamicSharedMemorySize, GEMM_SMEM);
    cudaFuncSetAttribute(bf16gemm_kernel<192,192,true, false>, cudaFuncAttributeMaxDynamicSharedMemorySize, GEMM_SMEM);

    // 1) weight prep
    fold_w_kernel<<<(192 * 384 + 255) / 256, 256>>>(proj_w, msg0_w);
    fold_b_kernel<<<2, 192>>>(proj_b, msg0_w, msg0_b);
    transpose_bf16_kernel<<<(192 * 384 + 255) / 256, 256>>>(msg0_w + 192 * 384, pWbT, 192, 384);
    transpose_bf16_kernel<<<(384 * 384 + 255) / 256, 256>>>(msg1_w, pWt1, 384, 384);
    transpose_bf16_kernel<<<(384 * 192 + 255) / 256, 256>>>(msg2_w, pWt2, 384, 192);
    transpose_bf16_kernel<<<(192 * 192 + 255) / 256, 256>>>(pred0_w, pWp0T, 192, 192);

    // 2) input conversions
    cvt_bf16_kernel<<<(S * 192 / 4 + 255) / 256, 256>>>(x, pXh, S * 192 / 4);
    qe_kernel<<<(NQ * 192 + 255) / 256, 256>>>(qpos);

    // 3) A1 = x @ Wc + bc   [S, 384] fp32
    bf16gemm_kernel<384,192,false,false><<<dim3(3, S / 128), 256, GEMM_SMEM>>>(pXh, pWcT, pbc, pA1);

    // 4) A2 = QE @ msg0_w_bot   [NQ, 384] fp32
    bf16gemm_kernel<384,192,false,false><<<dim3(3, NQ / 128), 256, GEMM_SMEM>>>(pQEh, pWbT, nullptr, pA2);

    // 5) H0 = bf16(gelu(A1[g] + A2[q]))  [NE, 384]
    edge0_kernel<<<(NE * 48 + 255) / 256, 256>>>(edges);

    // 6) H1 = bf16(gelu(H0 @ msg1_w + b1))  [NE, 384]
    bf16gemm_kernel<384,384,true,true><<<dim3(3, NE / 128), 256, GEMM_SMEM>>>(pH0h, pWt1, msg1_b, pH1h);

    // 7) H2 = bf16(H1 @ msg2_w + b2)  [NE, 192]  (into reused H0 buffer)
    bf16gemm_kernel<192,384,false,true><<<dim3(2, NE / 128), 256, GEMM_SMEM>>>(pH1h, pWt2, msg2_b, pH2h);

    // 8) segment offsets + mean -> M bf16
    segstart_kernel<<<(NQ + 1 + 255) / 256, 256>>>(edges);
    segmean_kernel<<<NQ, 192>>>(pH2h);

    // 9) T = gelu(M @ pred0_w + pred0_b)  [NQ, 192] fp32
    bf16gemm_kernel<192,192,true,false><<<dim3(2, NQ / 128), 256, GEMM_SMEM>>>(pMh, pWp0T, pred0_b, pT);

    // 10) out = T @ pred1_w + pred1_b  [NQ, 4]
    outk_kernel<<<(NQ * 4 + 127) / 128, 128>>>(pred1_w, pred1_b, out);
}